// round 11
// baseline (speedup 1.0000x reference)
#include <cuda_runtime.h>
#include <cstdint>

#define NB 8192           // batch
#define A1W 286           // 11*26 conv1 output pixels per batch elem

#define MAJ3(a,b,c) (((a)&(b)) | ((c)&((a)|(b))))
#define XOR3(a,b,c) ((a)^(b)^(c))

// ---------------- scratch (device globals; no allocation allowed) ----------
__device__ uint32_t g_lut1[512];                       // conv1+bn1+relu+binarize LUT
__device__ uint32_t g_wpos2[64 * 9];                   // conv2 weight sign bits [oc][tap]
__device__ float    g_c1_2[64], g_c0_2[64];            // conv2 bn affine
__device__ __align__(16) uint32_t g_wposL[512 * 128];  // lin weight bits [n(pad512)][j(pad128)]
__device__ uint32_t g_wposO[10 * 16];                  // out weight bits [k][g]
__device__ uint32_t g_A1[NB * A1W];                    // conv1 output, 32ch packed per pixel
__device__ uint32_t g_tT[120 * NB];                    // conv2 output bits, transposed [j][m]
__device__ __align__(16) uint32_t g_B2[NB * 16];       // lin output bits [m][16 words]

// ---------------- prep (misc): LUTs, conv2 weights, out weights ------------
__global__ void prep_misc_kernel(const float* __restrict__ conv1_w, const float* __restrict__ conv1_b,
                                 const float* __restrict__ bn1_g, const float* __restrict__ bn1_b,
                                 const float* __restrict__ bn1_m, const float* __restrict__ bn1_v,
                                 const float* __restrict__ conv2_w, const float* __restrict__ conv2_b,
                                 const float* __restrict__ bn2_g, const float* __restrict__ bn2_b,
                                 const float* __restrict__ bn2_m, const float* __restrict__ bn2_v,
                                 const float* __restrict__ out_w)
{
    int t = threadIdx.x;
    __shared__ uint32_t wb1[32];
    __shared__ float c1s[32], c0s[32];
    if (t < 32) {
        uint32_t wb = 0;
        #pragma unroll
        for (int k = 0; k < 9; k++) wb |= (conv1_w[t * 9 + k] > 0.0f) ? (1u << k) : 0u;
        wb1[t] = wb;
        float inv = __fdiv_rn(bn1_g[t], __fsqrt_rn(bn1_v[t] + 1e-5f));
        c1s[t] = inv;
        c0s[t] = conv1_b[t] * inv + bn1_b[t] - bn1_m[t] * inv;
    }
    __syncthreads();
    for (int idx = t; idx < 512; idx += 256) {
        uint32_t word = 0;
        #pragma unroll
        for (int oc = 0; oc < 32; oc++) {
            int pb = __popc((uint32_t)idx ^ wb1[oc]);
            float s = (float)(9 - 2 * pb);
            float val = fmaf(s, c1s[oc], c0s[oc]);
            if (val > 0.0f) word |= (1u << oc);
        }
        g_lut1[idx] = word;
    }
    for (int e = t; e < 576; e += 256) {
        int oc = e / 9, tap = e % 9;
        uint32_t w = 0;
        #pragma unroll
        for (int c = 0; c < 32; c++)
            w |= (conv2_w[oc * 288 + c * 9 + tap] > 0.0f) ? (1u << c) : 0u;
        g_wpos2[e] = w;
    }
    if (t < 64) {
        float inv = __fdiv_rn(bn2_g[t], __fsqrt_rn(bn2_v[t] + 1e-5f));
        g_c1_2[t] = inv;
        g_c0_2[t] = conv2_b[t] * inv + bn2_b[t] - bn2_m[t] * inv;
    }
    if (t < 160) {
        int k = t / 16, g = t % 16;
        uint32_t w = 0;
        #pragma unroll
        for (int b2 = 0; b2 < 32; b2++) {
            int n = g * 32 + b2;
            if (n < 500 && out_w[k * 500 + n] > 0.0f) w |= (1u << b2);
        }
        g_wposO[t] = w;
    }
}

// ---------------- prep (lin): coalesced read + smem transpose pack ---------
__global__ void prep_lin_kernel(const float* __restrict__ lin_w)
{
    __shared__ uint8_t sb[3840];
    int n = blockIdx.x;                 // 0..499
    const float* row = lin_w + n * 3840;
    for (int i = threadIdx.x; i < 3840; i += 256)
        sb[i] = row[i] > 0.0f ? 1 : 0;
    __syncthreads();
    for (int j = threadIdx.x; j < 128; j += 256) {
        uint32_t w = 0;
        if (j < 120) {
            int sp = j >> 1;
            int cb = (j & 1) * 32;
            #pragma unroll
            for (int b = 0; b < 32; b++)
                w |= (uint32_t)sb[(cb + b) * 60 + sp] << b;
        }
        g_wposL[n * 128 + j] = w;
    }
}

// ---------------- conv1: sign-pack x + 9-bit-patch LUT --------------------
__global__ void conv1_kernel(const float* __restrict__ x)
{
    __shared__ uint32_t rb[24][2];
    __shared__ uint32_t lut[512];
    int t = threadIdx.x;
    int b = blockIdx.x;
    int lane = t & 31, w = t >> 5;
    #pragma unroll
    for (int i = 0; i < 4; i++) lut[t + i * 128] = g_lut1[t + i * 128];
    const float* xb = x + b * 1296;
    for (int r = w; r < 24; r += 4) {
        const float* xr = xb + r * 54;
        uint32_t m0 = __ballot_sync(0xffffffffu, xr[lane] > 0.0f);
        float v2 = (lane < 22) ? xr[32 + lane] : -1.0f;
        uint32_t m1 = __ballot_sync(0xffffffffu, v2 > 0.0f);
        if (lane == 0) { rb[r][0] = m0; rb[r][1] = m1; }
    }
    __syncthreads();
    for (int p = t; p < A1W; p += 128) {
        int oy = p / 26, ox = p % 26;
        int sh = 2 * ox;
        uint32_t idx = 0;
        #pragma unroll
        for (int i = 0; i < 3; i++) {
            int r = 2 * oy + i;
            uint64_t row = (uint64_t)rb[r][0] | ((uint64_t)rb[r][1] << 32);
            idx |= (((uint32_t)(row >> sh)) & 7u) << (3 * i);
        }
        g_A1[b * A1W + p] = lut[idx];
    }
}

// ---------------- conv2: CSA conv, 7-col windows, low-reg (occ 8 blk/SM) ---
__global__ void __launch_bounds__(128, 8) conv2_kernel()
{
    __shared__ uint32_t sA[4][288];
    __shared__ uint32_t sO[120][4];
    __shared__ uint32_t sW[576];
    int t = threadIdx.x, warp = t >> 5, lane = t & 31;
    int b0 = blockIdx.x * 4;

    for (int i = t; i < 4 * A1W; i += 128) {
        int e = i / A1W, p = i - e * A1W;
        sA[e][p] = g_A1[(b0 + e) * A1W + p];
    }
    for (int i = t; i < 576; i += 128) sW[i] = g_wpos2[i];

    uint32_t w0[9];
    #pragma unroll
    for (int k = 0; k < 9; k++) w0[k] = g_wpos2[lane * 9 + k];
    float c1a = g_c1_2[lane], c0a = g_c0_2[lane];
    float c1b = g_c1_2[lane + 32], c0b = g_c0_2[lane + 32];
    __syncthreads();

    const uint32_t* A = sA[warp];
    const uint32_t* W1 = &sW[(lane + 32) * 9];   // conflict-free: stride 9 words
    #pragma unroll 1
    for (int oy = 0; oy < 5; oy++) {
        const uint32_t* R = A + oy * 52;
        #pragma unroll 1
        for (int gw = 0; gw < 4; gw++) {
            int cb = gw * 6;
            uint32_t v[3][7];
            #pragma unroll
            for (int i = 0; i < 3; i++)
                #pragma unroll
                for (int c = 0; c < 7; c++)
                    v[i][c] = R[i * 26 + cb + c];
            uint32_t psc[7];                     // popc(s) | popc(c)<<16
            #pragma unroll
            for (int c = 0; c < 7; c++) {
                uint32_t s = XOR3(v[0][c], v[1][c], v[2][c]);
                uint32_t cc = MAJ3(v[0][c], v[1][c], v[2][c]);
                psc[c] = (uint32_t)__popc(s) + ((uint32_t)__popc(cc) << 16);
            }
            #pragma unroll
            for (int px = 0; px < 3; px++) {
                int c0 = px * 2;
                uint32_t ap = psc[c0] + psc[c0 + 1] + psc[c0 + 2];
                int Asum = (int)(ap & 0xFFFFu) + 2 * (int)(ap >> 16);
                int P0, P1;
                {
                    uint32_t t0 = v[0][c0] & w0[0], t1 = v[0][c0+1] & w0[1], t2 = v[0][c0+2] & w0[2];
                    uint32_t t3 = v[1][c0] & w0[3], t4 = v[1][c0+1] & w0[4], t5 = v[1][c0+2] & w0[5];
                    uint32_t t6 = v[2][c0] & w0[6], t7 = v[2][c0+1] & w0[7], t8 = v[2][c0+2] & w0[8];
                    uint32_t s1 = XOR3(t0,t1,t2), cA = MAJ3(t0,t1,t2);
                    uint32_t s2 = XOR3(t3,t4,t5), cB = MAJ3(t3,t4,t5);
                    uint32_t s3 = XOR3(t6,t7,t8), cC = MAJ3(t6,t7,t8);
                    uint32_t Sx = XOR3(s1,s2,s3), C2 = MAJ3(s1,s2,s3);
                    uint32_t S2 = XOR3(cA,cB,cC), C4 = MAJ3(cA,cB,cC);
                    P0 = __popc(Sx) + 2 * (__popc(C2) + __popc(S2)) + 4 * __popc(C4);
                }
                {
                    uint32_t t0 = v[0][c0] & W1[0], t1 = v[0][c0+1] & W1[1], t2 = v[0][c0+2] & W1[2];
                    uint32_t t3 = v[1][c0] & W1[3], t4 = v[1][c0+1] & W1[4], t5 = v[1][c0+2] & W1[5];
                    uint32_t t6 = v[2][c0] & W1[6], t7 = v[2][c0+1] & W1[7], t8 = v[2][c0+2] & W1[8];
                    uint32_t s1 = XOR3(t0,t1,t2), cA = MAJ3(t0,t1,t2);
                    uint32_t s2 = XOR3(t3,t4,t5), cB = MAJ3(t3,t4,t5);
                    uint32_t s3 = XOR3(t6,t7,t8), cC = MAJ3(t6,t7,t8);
                    uint32_t Sx = XOR3(s1,s2,s3), C2 = MAJ3(s1,s2,s3);
                    uint32_t S2 = XOR3(cA,cB,cC), C4 = MAJ3(cA,cB,cC);
                    P1 = __popc(Sx) + 2 * (__popc(C2) + __popc(S2)) + 4 * __popc(C4);
                }
                float f0 = fmaf((float)(2 * P0 - Asum), c1a, c0a);
                float f1 = fmaf((float)(2 * P1 - Asum), c1b, c0b);
                uint32_t m0 = __ballot_sync(0xffffffffu, f0 > 0.0f);
                uint32_t m1 = __ballot_sync(0xffffffffu, f1 > 0.0f);
                int sp = oy * 12 + gw * 3 + px;
                if (lane == 0) sO[2 * sp][warp] = m0;
                if (lane == 1) sO[2 * sp + 1][warp] = m1;
            }
        }
    }
    __syncthreads();

    for (int i = t; i < 480; i += 128) {
        int j = i >> 2, u = i & 3;
        g_tT[j * NB + b0 + u] = sO[j][u];
    }
}

// ---------------- lin: 2-level CSA GEMM, 12-word chunks (low-reg) ----------
// block = 128 thr = 4 warps covering 128 m x 16 n; grid = 64 m-tiles x 32 ng = 2048.
__global__ void __launch_bounds__(128) lin_kernel(const float* __restrict__ lin_b)
{
    __shared__ uint4 sw[16][30];        // 16 n rows x 120 words = 7.7 KB
    __shared__ float sbias[16];
    int t = threadIdx.x;
    int ng = blockIdx.x & 31;           // 16-n group
    int mg = (blockIdx.x >> 5) * 4 + (t >> 5);
    int lane = t & 31;

    const uint4* wsrc = reinterpret_cast<const uint4*>(g_wposL) + (ng * 16) * 32;
    for (int i = t; i < 480; i += 128) {
        int n = i / 30, q = i - n * 30;
        sw[n][q] = wsrc[n * 32 + q];
    }
    if (t < 16) {
        int gn = ng * 16 + t;
        sbias[t] = (gn < 500) ? lin_b[gn] : 0.0f;
    }
    __syncthreads();

    int m = mg * 32 + lane;
    int acc[16];
    #pragma unroll
    for (int n = 0; n < 16; n++) acc[n] = 0;
    int S = 0;

    #pragma unroll 1
    for (int kc = 0; kc < 10; kc++) {   // 10 chunks x 12 words
        uint32_t tw[12];
        #pragma unroll
        for (int u = 0; u < 12; u++) tw[u] = g_tT[(kc * 12 + u) * NB + m];
        {
            int ss = 0, sc = 0;
            #pragma unroll
            for (int g = 0; g < 4; g++) {
                ss += __popc(XOR3(tw[3*g], tw[3*g+1], tw[3*g+2]));
                sc += __popc(MAJ3(tw[3*g], tw[3*g+1], tw[3*g+2]));
            }
            S += ss + 2 * sc;
        }
        #pragma unroll 4
        for (int n = 0; n < 16; n++) {
            uint32_t w[12];
            #pragma unroll
            for (int q = 0; q < 3; q++) {
                uint4 wv = sw[n][kc * 3 + q];
                w[q*4+0] = wv.x; w[q*4+1] = wv.y; w[q*4+2] = wv.z; w[q*4+3] = wv.w;
            }
            uint32_t s[4], c[4];
            #pragma unroll
            for (int g = 0; g < 4; g++) {
                uint32_t t0 = tw[3*g]   & w[3*g];
                uint32_t t1 = tw[3*g+1] & w[3*g+1];
                uint32_t t2 = tw[3*g+2] & w[3*g+2];
                s[g] = XOR3(t0, t1, t2);
                c[g] = MAJ3(t0, t1, t2);
            }
            uint32_t a1 = XOR3(s[0], s[1], s[2]), b1 = MAJ3(s[0], s[1], s[2]);
            uint32_t d1 = XOR3(c[0], c[1], c[2]), e1 = MAJ3(c[0], c[1], c[2]);
            acc[n] += (__popc(a1) + __popc(s[3]))
                    + 2 * (__popc(b1) + __popc(d1) + __popc(c[3]))
                    + 4 * __popc(e1);
        }
    }

    uint32_t bits = 0;
    #pragma unroll
    for (int n = 0; n < 16; n++) {
        int gn = ng * 16 + n;
        if (gn < 500) {
            float pre = (float)(2 * acc[n] - S) + sbias[n];
            if (pre > 0.0f) bits |= (1u << n);
        }
    }
    reinterpret_cast<uint16_t*>(g_B2)[m * 32 + ng] = (uint16_t)bits;
}

// ---------------- out: 500->10 popcount matmul -----------------------------
__global__ void out_kernel(const float* __restrict__ out_b, float* __restrict__ y)
{
    __shared__ uint32_t wO[160];
    __shared__ float ob[10];
    int t = threadIdx.x;
    if (t < 160) wO[t] = g_wposO[t];
    if (t < 10)  ob[t] = out_b[t];
    __syncthreads();
    int m = blockIdx.x * 256 + t;
    uint32_t tw[16];
    const uint4* p = reinterpret_cast<const uint4*>(g_B2 + m * 16);
    #pragma unroll
    for (int q = 0; q < 4; q++) {
        uint4 v = p[q];
        tw[q * 4 + 0] = v.x; tw[q * 4 + 1] = v.y;
        tw[q * 4 + 2] = v.z; tw[q * 4 + 3] = v.w;
    }
    int S2 = 0;
    #pragma unroll
    for (int g = 0; g < 16; g++) S2 += __popc(tw[g]);
    #pragma unroll
    for (int k = 0; k < 10; k++) {
        int acc = 0;
        #pragma unroll
        for (int g = 0; g < 16; g++) acc += __popc(tw[g] & wO[k * 16 + g]);
        y[m * 10 + k] = (float)(2 * acc - S2) + ob[k];
    }
}

// ---------------- launch ----------------------------------------------------
extern "C" void kernel_launch(void* const* d_in, const int* in_sizes, int n_in,
                              void* d_out, int out_size)
{
    const float* x       = (const float*)d_in[0];
    const float* conv1_w = (const float*)d_in[1];
    const float* conv1_b = (const float*)d_in[2];
    const float* bn1_g   = (const float*)d_in[3];
    const float* bn1_b   = (const float*)d_in[4];
    const float* bn1_m   = (const float*)d_in[5];
    const float* bn1_v   = (const float*)d_in[6];
    const float* conv2_w = (const float*)d_in[7];
    const float* conv2_b = (const float*)d_in[8];
    const float* bn2_g   = (const float*)d_in[9];
    const float* bn2_b   = (const float*)d_in[10];
    const float* bn2_m   = (const float*)d_in[11];
    const float* bn2_v   = (const float*)d_in[12];
    const float* lin_w   = (const float*)d_in[13];
    const float* lin_b   = (const float*)d_in[14];
    const float* out_w   = (const float*)d_in[15];
    const float* out_b   = (const float*)d_in[16];

    prep_misc_kernel<<<1, 256>>>(conv1_w, conv1_b, bn1_g, bn1_b, bn1_m, bn1_v,
                                 conv2_w, conv2_b, bn2_g, bn2_b, bn2_m, bn2_v,
                                 out_w);
    prep_lin_kernel<<<500, 256>>>(lin_w);
    conv1_kernel<<<NB, 128>>>(x);
    conv2_kernel<<<NB / 4, 128>>>();
    lin_kernel<<<2048, 128>>>(lin_b);
    out_kernel<<<NB / 256, 256>>>(out_b, (float*)d_out);
}

// round 12
// speedup vs baseline: 1.1115x; 1.1115x over previous
#include <cuda_runtime.h>
#include <cstdint>

#define NB 8192           // batch
#define A1W 286           // 11*26 conv1 output pixels per batch elem

#define MAJ3(a,b,c) (((a)&(b)) | ((c)&((a)|(b))))
#define XOR3(a,b,c) ((a)^(b)^(c))

// ---------------- scratch (device globals; no allocation allowed) ----------
__device__ uint32_t g_lut1[512];                       // conv1+bn1+relu+binarize LUT
__device__ uint32_t g_wpos2[64 * 9];                   // conv2 weight sign bits [oc][tap]
__device__ float    g_c1_2[64], g_c0_2[64];            // conv2 bn affine
__device__ __align__(16) uint32_t g_wposL[512 * 128];  // lin weight bits [n(pad512)][j(pad128)]
__device__ uint32_t g_wposO[10 * 16];                  // out weight bits [k][g]
__device__ uint32_t g_tT[120 * NB];                    // conv2 output bits, transposed [j][m]
__device__ __align__(16) uint32_t g_B2[NB * 16];       // lin output bits [m][16 words]

// ---------------- prep (merged): LUTs, conv2/out weights + lin pack --------
__global__ void prep_all_kernel(const float* __restrict__ conv1_w, const float* __restrict__ conv1_b,
                                const float* __restrict__ bn1_g, const float* __restrict__ bn1_b,
                                const float* __restrict__ bn1_m, const float* __restrict__ bn1_v,
                                const float* __restrict__ conv2_w, const float* __restrict__ conv2_b,
                                const float* __restrict__ bn2_g, const float* __restrict__ bn2_b,
                                const float* __restrict__ bn2_m, const float* __restrict__ bn2_v,
                                const float* __restrict__ lin_w, const float* __restrict__ out_w)
{
    int t = threadIdx.x;
    if (blockIdx.x < 500) {
        // lin weight packing: coalesced read + smem transpose
        __shared__ uint8_t sb[3840];
        int n = blockIdx.x;
        const float* row = lin_w + n * 3840;
        for (int i = t; i < 3840; i += 256)
            sb[i] = row[i] > 0.0f ? 1 : 0;
        __syncthreads();
        for (int j = t; j < 128; j += 256) {
            uint32_t w = 0;
            if (j < 120) {
                int sp = j >> 1;
                int cb = (j & 1) * 32;
                #pragma unroll
                for (int b = 0; b < 32; b++)
                    w |= (uint32_t)sb[(cb + b) * 60 + sp] << b;
            }
            g_wposL[n * 128 + j] = w;
        }
        return;
    }
    // misc block
    __shared__ uint32_t wb1[32];
    __shared__ float c1s[32], c0s[32];
    if (t < 32) {
        uint32_t wb = 0;
        #pragma unroll
        for (int k = 0; k < 9; k++) wb |= (conv1_w[t * 9 + k] > 0.0f) ? (1u << k) : 0u;
        wb1[t] = wb;
        float inv = __fdiv_rn(bn1_g[t], __fsqrt_rn(bn1_v[t] + 1e-5f));
        c1s[t] = inv;
        c0s[t] = conv1_b[t] * inv + bn1_b[t] - bn1_m[t] * inv;
    }
    __syncthreads();
    for (int idx = t; idx < 512; idx += 256) {
        uint32_t word = 0;
        #pragma unroll
        for (int oc = 0; oc < 32; oc++) {
            int pb = __popc((uint32_t)idx ^ wb1[oc]);
            float s = (float)(9 - 2 * pb);
            float val = fmaf(s, c1s[oc], c0s[oc]);
            if (val > 0.0f) word |= (1u << oc);
        }
        g_lut1[idx] = word;
    }
    for (int e = t; e < 576; e += 256) {
        int oc = e / 9, tap = e % 9;
        uint32_t w = 0;
        #pragma unroll
        for (int c = 0; c < 32; c++)
            w |= (conv2_w[oc * 288 + c * 9 + tap] > 0.0f) ? (1u << c) : 0u;
        g_wpos2[e] = w;
    }
    if (t < 64) {
        float inv = __fdiv_rn(bn2_g[t], __fsqrt_rn(bn2_v[t] + 1e-5f));
        g_c1_2[t] = inv;
        g_c0_2[t] = conv2_b[t] * inv + bn2_b[t] - bn2_m[t] * inv;
    }
    if (t < 160) {
        int k = t / 16, g = t % 16;
        uint32_t w = 0;
        #pragma unroll
        for (int b2 = 0; b2 < 32; b2++) {
            int n = g * 32 + b2;
            if (n < 500 && out_w[k * 500 + n] > 0.0f) w |= (1u << b2);
        }
        g_wposO[t] = w;
    }
}

// ---------------- conv12: fused conv1(LUT) + conv2(CSA), warp = batch elem -
// block = 128 thr = 4 warps = 4 elems; grid = NB/4 = 2048
__global__ void __launch_bounds__(128) conv12_kernel(const float* __restrict__ x)
{
    __shared__ float sX[4 * 1296];      // 20.25 KB staged input
    __shared__ uint32_t sA[4][288];     // conv1 output words
    __shared__ uint32_t sO[120][4];     // conv2 output bits staging
    __shared__ uint32_t lut[512];
    __shared__ uint32_t rw[4][24][2];   // sign-packed rows
    int t = threadIdx.x, warp = t >> 5, lane = t & 31;
    int b0 = blockIdx.x * 4;

    for (int i = t; i < 512; i += 128) lut[i] = g_lut1[i];
    {
        const float4* xs = reinterpret_cast<const float4*>(x + (size_t)b0 * 1296);
        float4* dst = reinterpret_cast<float4*>(sX);
        for (int i = t; i < 1296; i += 128) dst[i] = xs[i];
    }
    uint32_t w0[9], w1[9];
    #pragma unroll
    for (int k = 0; k < 9; k++) {
        w0[k] = g_wpos2[lane * 9 + k];
        w1[k] = g_wpos2[(lane + 32) * 9 + k];
    }
    float c1a = g_c1_2[lane], c0a = g_c0_2[lane];
    float c1b = g_c1_2[lane + 32], c0b = g_c0_2[lane + 32];
    __syncthreads();

    // ---- conv1: sign-pack rows (warp-local elem) ----
    const float* xe = sX + warp * 1296;
    for (int r = 0; r < 24; r++) {
        uint32_t m0 = __ballot_sync(0xffffffffu, xe[r * 54 + lane] > 0.0f);
        float v2 = (lane < 22) ? xe[r * 54 + 32 + lane] : -1.0f;
        uint32_t m1 = __ballot_sync(0xffffffffu, v2 > 0.0f);
        if (lane == 0) { rw[warp][r][0] = m0; rw[warp][r][1] = m1; }
    }
    __syncwarp();
    // ---- conv1: 9-bit patch LUT -> sA ----
    for (int p = lane; p < A1W; p += 32) {
        int oy = p / 26, ox = p - oy * 26;
        int sh = 2 * ox;
        uint32_t idx = 0;
        #pragma unroll
        for (int i = 0; i < 3; i++) {
            uint64_t row = *reinterpret_cast<const uint64_t*>(&rw[warp][2 * oy + i][0]);
            idx |= (((uint32_t)(row >> sh)) & 7u) << (3 * i);
        }
        sA[warp][p] = lut[idx];
    }
    __syncwarp();

    // ---- conv2: CSA popcount conv (R9/R10 body) ----
    const uint32_t* A = sA[warp];
    #pragma unroll 1
    for (int oy = 0; oy < 5; oy++) {
        const uint32_t* R = A + oy * 52;
        #pragma unroll
        for (int g = 0; g < 2; g++) {
            uint32_t v[3][13];
            #pragma unroll
            for (int i = 0; i < 3; i++)
                #pragma unroll
                for (int c = 0; c < 13; c++)
                    v[i][c] = R[i * 26 + g * 12 + c];
            int pS[13], pC[13];
            #pragma unroll
            for (int c = 0; c < 13; c++) {
                uint32_t s = XOR3(v[0][c], v[1][c], v[2][c]);
                uint32_t cc = MAJ3(v[0][c], v[1][c], v[2][c]);
                pS[c] = __popc(s);
                pC[c] = __popc(cc);
            }
            #pragma unroll
            for (int px = 0; px < 6; px++) {
                int c0 = px * 2;
                int Asum = (pS[c0] + pS[c0 + 1] + pS[c0 + 2])
                         + 2 * (pC[c0] + pC[c0 + 1] + pC[c0 + 2]);
                int P0, P1;
                {
                    uint32_t t0 = v[0][c0] & w0[0], t1 = v[0][c0+1] & w0[1], t2 = v[0][c0+2] & w0[2];
                    uint32_t t3 = v[1][c0] & w0[3], t4 = v[1][c0+1] & w0[4], t5 = v[1][c0+2] & w0[5];
                    uint32_t t6 = v[2][c0] & w0[6], t7 = v[2][c0+1] & w0[7], t8 = v[2][c0+2] & w0[8];
                    uint32_t s1 = XOR3(t0,t1,t2), cA = MAJ3(t0,t1,t2);
                    uint32_t s2 = XOR3(t3,t4,t5), cB = MAJ3(t3,t4,t5);
                    uint32_t s3 = XOR3(t6,t7,t8), cC = MAJ3(t6,t7,t8);
                    uint32_t Sx = XOR3(s1,s2,s3), C2 = MAJ3(s1,s2,s3);
                    uint32_t S2 = XOR3(cA,cB,cC), C4 = MAJ3(cA,cB,cC);
                    P0 = __popc(Sx) + 2 * (__popc(C2) + __popc(S2)) + 4 * __popc(C4);
                }
                {
                    uint32_t t0 = v[0][c0] & w1[0], t1 = v[0][c0+1] & w1[1], t2 = v[0][c0+2] & w1[2];
                    uint32_t t3 = v[1][c0] & w1[3], t4 = v[1][c0+1] & w1[4], t5 = v[1][c0+2] & w1[5];
                    uint32_t t6 = v[2][c0] & w1[6], t7 = v[2][c0+1] & w1[7], t8 = v[2][c0+2] & w1[8];
                    uint32_t s1 = XOR3(t0,t1,t2), cA = MAJ3(t0,t1,t2);
                    uint32_t s2 = XOR3(t3,t4,t5), cB = MAJ3(t3,t4,t5);
                    uint32_t s3 = XOR3(t6,t7,t8), cC = MAJ3(t6,t7,t8);
                    uint32_t Sx = XOR3(s1,s2,s3), C2 = MAJ3(s1,s2,s3);
                    uint32_t S2 = XOR3(cA,cB,cC), C4 = MAJ3(cA,cB,cC);
                    P1 = __popc(Sx) + 2 * (__popc(C2) + __popc(S2)) + 4 * __popc(C4);
                }
                float f0 = fmaf((float)(2 * P0 - Asum), c1a, c0a);
                float f1 = fmaf((float)(2 * P1 - Asum), c1b, c0b);
                uint32_t m0 = __ballot_sync(0xffffffffu, f0 > 0.0f);
                uint32_t m1 = __ballot_sync(0xffffffffu, f1 > 0.0f);
                int sp = oy * 12 + g * 6 + px;
                if (lane == 0) sO[2 * sp][warp] = m0;
                if (lane == 1) sO[2 * sp + 1][warp] = m1;
            }
        }
    }
    __syncthreads();

    for (int i = t; i < 480; i += 128) {
        int j = i >> 2, u = i & 3;
        g_tT[j * NB + b0 + u] = sO[j][u];
    }
}

// ---------------- lin: 2-level CSA popcount GEMM (R10 version) -------------
// block = 128 thr = 4 warps covering 128 m x 16 n; grid = 64 m-tiles x 32 ng = 2048.
__global__ void __launch_bounds__(128) lin_kernel(const float* __restrict__ lin_b)
{
    __shared__ uint4 sw[16][30];        // 16 n rows x 120 words = 7.7 KB
    __shared__ float sbias[16];
    int t = threadIdx.x;
    int ng = blockIdx.x & 31;           // 16-n group
    int mg = (blockIdx.x >> 5) * 4 + (t >> 5);
    int lane = t & 31;

    const uint4* wsrc = reinterpret_cast<const uint4*>(g_wposL) + (ng * 16) * 32;
    for (int i = t; i < 480; i += 128) {
        int n = i / 30, q = i - n * 30;
        sw[n][q] = wsrc[n * 32 + q];
    }
    if (t < 16) {
        int gn = ng * 16 + t;
        sbias[t] = (gn < 500) ? lin_b[gn] : 0.0f;
    }
    __syncthreads();

    int m = mg * 32 + lane;
    int acc[16];
    #pragma unroll
    for (int n = 0; n < 16; n++) acc[n] = 0;
    int S = 0;

    #pragma unroll 1
    for (int kc = 0; kc < 5; kc++) {
        uint32_t tw[24];
        #pragma unroll
        for (int u = 0; u < 24; u++) tw[u] = g_tT[(kc * 24 + u) * NB + m];
        {
            int ss = 0, sc = 0;
            #pragma unroll
            for (int g = 0; g < 8; g++) {
                uint32_t a0 = tw[3*g], a1 = tw[3*g+1], a2 = tw[3*g+2];
                ss += __popc(XOR3(a0, a1, a2));
                sc += __popc(MAJ3(a0, a1, a2));
            }
            S += ss + 2 * sc;
        }
        #pragma unroll 4
        for (int n = 0; n < 16; n++) {
            uint32_t w[24];
            #pragma unroll
            for (int q = 0; q < 6; q++) {
                uint4 wv = sw[n][kc * 6 + q];
                w[q*4+0] = wv.x; w[q*4+1] = wv.y; w[q*4+2] = wv.z; w[q*4+3] = wv.w;
            }
            uint32_t s[8], c[8];
            #pragma unroll
            for (int g = 0; g < 8; g++) {
                uint32_t t0 = tw[3*g]   & w[3*g];
                uint32_t t1 = tw[3*g+1] & w[3*g+1];
                uint32_t t2 = tw[3*g+2] & w[3*g+2];
                s[g] = XOR3(t0, t1, t2);
                c[g] = MAJ3(t0, t1, t2);
            }
            uint32_t a1 = XOR3(s[0], s[1], s[2]), b1 = MAJ3(s[0], s[1], s[2]);
            uint32_t a2 = XOR3(s[3], s[4], s[5]), b2 = MAJ3(s[3], s[4], s[5]);
            uint32_t d1 = XOR3(c[0], c[1], c[2]), e1 = MAJ3(c[0], c[1], c[2]);
            uint32_t d2 = XOR3(c[3], c[4], c[5]), e2 = MAJ3(c[3], c[4], c[5]);
            int p1 = __popc(a1) + __popc(a2) + __popc(s[6]) + __popc(s[7]);
            int p2 = __popc(b1) + __popc(b2) + __popc(d1) + __popc(d2)
                   + __popc(c[6]) + __popc(c[7]);
            int p4 = __popc(e1) + __popc(e2);
            acc[n] += p1 + 2 * p2 + 4 * p4;
        }
    }

    uint32_t bits = 0;
    #pragma unroll
    for (int n = 0; n < 16; n++) {
        int gn = ng * 16 + n;
        if (gn < 500) {
            float pre = (float)(2 * acc[n] - S) + sbias[n];
            if (pre > 0.0f) bits |= (1u << n);
        }
    }
    reinterpret_cast<uint16_t*>(g_B2)[m * 32 + ng] = (uint16_t)bits;
}

// ---------------- out: 500->10 popcount matmul -----------------------------
__global__ void out_kernel(const float* __restrict__ out_b, float* __restrict__ y)
{
    __shared__ uint32_t wO[160];
    __shared__ float ob[10];
    int t = threadIdx.x;
    if (t < 160) wO[t] = g_wposO[t];
    if (t < 10)  ob[t] = out_b[t];
    __syncthreads();
    int m = blockIdx.x * 256 + t;
    uint32_t tw[16];
    const uint4* p = reinterpret_cast<const uint4*>(g_B2 + m * 16);
    #pragma unroll
    for (int q = 0; q < 4; q++) {
        uint4 v = p[q];
        tw[q * 4 + 0] = v.x; tw[q * 4 + 1] = v.y;
        tw[q * 4 + 2] = v.z; tw[q * 4 + 3] = v.w;
    }
    int S2 = 0;
    #pragma unroll
    for (int g = 0; g < 16; g++) S2 += __popc(tw[g]);
    #pragma unroll
    for (int k = 0; k < 10; k++) {
        int acc = 0;
        #pragma unroll
        for (int g = 0; g < 16; g++) acc += __popc(tw[g] & wO[k * 16 + g]);
        y[m * 10 + k] = (float)(2 * acc - S2) + ob[k];
    }
}

// ---------------- launch ----------------------------------------------------
extern "C" void kernel_launch(void* const* d_in, const int* in_sizes, int n_in,
                              void* d_out, int out_size)
{
    const float* x       = (const float*)d_in[0];
    const float* conv1_w = (const float*)d_in[1];
    const float* conv1_b = (const float*)d_in[2];
    const float* bn1_g   = (const float*)d_in[3];
    const float* bn1_b   = (const float*)d_in[4];
    const float* bn1_m   = (const float*)d_in[5];
    const float* bn1_v   = (const float*)d_in[6];
    const float* conv2_w = (const float*)d_in[7];
    const float* conv2_b = (const float*)d_in[8];
    const float* bn2_g   = (const float*)d_in[9];
    const float* bn2_b   = (const float*)d_in[10];
    const float* bn2_m   = (const float*)d_in[11];
    const float* bn2_v   = (const float*)d_in[12];
    const float* lin_w   = (const float*)d_in[13];
    const float* lin_b   = (const float*)d_in[14];
    const float* out_w   = (const float*)d_in[15];
    const float* out_b   = (const float*)d_in[16];

    prep_all_kernel<<<501, 256>>>(conv1_w, conv1_b, bn1_g, bn1_b, bn1_m, bn1_v,
                                  conv2_w, conv2_b, bn2_g, bn2_b, bn2_m, bn2_v,
                                  lin_w, out_w);
    conv12_kernel<<<NB / 4, 128>>>(x);
    lin_kernel<<<2048, 128>>>(lin_b);
    out_kernel<<<NB / 256, 256>>>(out_b, (float*)d_out);
}